// round 3
// baseline (speedup 1.0000x reference)
#include <cuda_runtime.h>

#define FULLMASK 0xffffffffu

// ---------------- scratch (device globals; no allocations allowed) ----------
__device__ float g_cyc[1024 * 8];
__device__ float g_q[1024 * 8];
__device__ float g_k[1024 * 8];
__device__ float g_v[1024 * 8];
__device__ float g_coll[1024 * 8];
__device__ float g_lg[1024];
__device__ int   g_cnt = 0;

__device__ __forceinline__ float safef(float x) {
    x = (x != x) ? 0.f : x;                    // nan -> 0
    return fminf(fmaxf(x, -10000.f), 10000.f); // +-inf -> clamp
}
__device__ __forceinline__ float dot4(float4 a, float4 b) {
    return a.x * b.x + a.y * b.y + a.z * b.z + a.w * b.w;
}

// =====================================================================
// K1: per-cycle pipeline. 1 block = 1 cycle, 256 threads = 256 darts.
// =====================================================================
__global__ void __launch_bounds__(256) cycle_kernel(
    const float* __restrict__ df,
    const float* __restrict__ de_w, const float* __restrict__ de_b,
    const float* __restrict__ ca_in_w, const float* __restrict__ ca_in_b,
    const float* __restrict__ ca_out_w, const float* __restrict__ ca_out_b,
    const float* __restrict__ cn_g, const float* __restrict__ cn_b,
    const float* __restrict__ cs_w, const float* __restrict__ cs_b,
    const float* __restrict__ cp_ln_g, const float* __restrict__ cp_ln_b,
    const float* __restrict__ cp_w1, const float* __restrict__ cp_b1,
    const float* __restrict__ cp_w2, const float* __restrict__ cp_b2,
    const float* __restrict__ ia_in_w, const float* __restrict__ ia_in_b)
{
    __shared__ float sdx[256], sdy[256];
    __shared__ __align__(16) float skv[256 * 20];   // per dart: k[0..7], v[8..15], pad4
    __shared__ __align__(16) float sW[736];
    __shared__ float red[8], red2[8], wred[64];

    int tid = threadIdx.x;
    int lane = tid & 31, warp = tid >> 5;
    int c = blockIdx.x;

    // ---- stage ALL per-block weights into shared
    if (tid < 192) { sW[tid] = ca_in_w[tid]; sW[512 + tid] = ia_in_w[tid]; }
    if (tid < 64)  { sW[216 + tid] = ca_out_w[tid]; sW[368 + tid] = cp_w1[tid]; sW[440 + tid] = cp_w2[tid]; }
    if (tid < 24)  { sW[192 + tid] = ca_in_b[tid]; sW[288 + tid] = de_w[tid]; sW[704 + tid] = ia_in_b[tid]; }
    if (tid < 8) {
        sW[280 + tid] = ca_out_b[tid];
        sW[312 + tid] = de_b[tid];
        sW[320 + tid] = cn_g[tid];
        sW[328 + tid] = cn_b[tid];
        sW[336 + tid] = cs_w[tid];
        sW[352 + tid] = cp_ln_g[tid];
        sW[360 + tid] = cp_ln_b[tid];
        sW[432 + tid] = cp_b1[tid];
        sW[504 + tid] = cp_b2[tid];
    }
    if (tid == 0) sW[344] = cs_b[0];

    // ---- coalesced load of this cycle's darts (skv as staging)
    const float* base = df + (size_t)c * 768;
    skv[tid]       = base[tid];
    skv[tid + 256] = base[tid + 256];
    skv[tid + 512] = base[tid + 512];
    __syncthreads();                                       // (1)

    float dx = skv[3 * tid];
    float dy = skv[3 * tid + 1];
    sdx[tid] = dx; sdy[tid] = dy;

    // ---- warp-shuffle inclusive scan for prefix sums (vertices)
    float sx = dx, sy = dy;
    #pragma unroll
    for (int off = 1; off < 32; off <<= 1) {
        float tx = __shfl_up_sync(FULLMASK, sx, off);
        float ty = __shfl_up_sync(FULLMASK, sy, off);
        if (lane >= off) { sx += tx; sy += ty; }
    }
    if (lane == 31) { red[warp] = sx; red2[warp] = sy; }
    __syncthreads();                                       // (2)
    float bx = 0.f, by = 0.f;
    #pragma unroll
    for (int w = 0; w < 8; ++w) {
        if (w < warp) { bx += red[w]; by += red2[w]; }
    }
    float Vx = bx + sx - dx, Vy = by + sy - dy;            // exclusive prefix
    float cr = (tid < 255) ? (Vx * dy - Vy * dx) : 0.f;
    #pragma unroll
    for (int off = 16; off; off >>= 1) cr += __shfl_xor_sync(FULLMASK, cr, off);
    if (lane == 0) wred[warp] = cr;
    __syncthreads();                                       // (3)
    float area = 0.f;
    #pragma unroll
    for (int w = 0; w < 8; ++w) area += wred[w];
    bool flip = area < 0.f;

    float ex = flip ? -sdx[255 - tid] : dx;
    float ey = flip ? -sdy[255 - tid] : dy;
    float fn = safef(sqrtf(ex * ex + ey * ey));
    float fx = safef(ex), fy = safef(ey);

    // ---- dart embed: relu(feats @ de_w.T + de_b), safe
    float emb[8];
    #pragma unroll
    for (int j = 0; j < 8; ++j) {
        float e = fx * sW[288 + 3 * j] + fy * sW[288 + 3 * j + 1] + fn * sW[288 + 3 * j + 2] + sW[312 + j];
        emb[j] = safef(fmaxf(e, 0.f));
    }

    // ---- qkv (24x8). q in regs; k,v into skv row.
    const float4* w4 = (const float4*)sW;
    float4 e0 = make_float4(emb[0], emb[1], emb[2], emb[3]);
    float4 e1 = make_float4(emb[4], emb[5], emb[6], emb[7]);
    float qv[8];
    #pragma unroll
    for (int j = 0; j < 8; ++j)
        qv[j] = dot4(e0, w4[2 * j]) + dot4(e1, w4[2 * j + 1]) + sW[192 + j];
    float* myrow = &skv[tid * 20];
    #pragma unroll
    for (int j = 8; j < 24; ++j)
        myrow[j - 8] = dot4(e0, w4[2 * j]) + dot4(e1, w4[2 * j + 1]) + sW[192 + j];
    __syncthreads();                                       // (4)

    // ---- 3-neighbor attention
    int im = (tid + 255) & 255, ip = (tid + 1) & 255;
    const float4* rm = (const float4*)&skv[im * 20];
    const float4* rc = (const float4*)&skv[tid * 20];
    const float4* rp = (const float4*)&skv[ip * 20];
    float4 qh0 = make_float4(qv[0], qv[1], qv[2], qv[3]);
    float4 qh1 = make_float4(qv[4], qv[5], qv[6], qv[7]);
    float o[8];
    {
        float4 k0 = rm[0], k1 = rc[0], k2 = rp[0];
        float s0 = 0.5f * dot4(qh0, k0), s1 = 0.5f * dot4(qh0, k1), s2 = 0.5f * dot4(qh0, k2);
        float mm = fmaxf(s0, fmaxf(s1, s2));
        float p0 = __expf(s0 - mm), p1 = __expf(s1 - mm), p2 = __expf(s2 - mm);
        float inv = 1.f / (p0 + p1 + p2);
        float4 v0 = rm[2], v1 = rc[2], v2 = rp[2];
        o[0] = (p0 * v0.x + p1 * v1.x + p2 * v2.x) * inv;
        o[1] = (p0 * v0.y + p1 * v1.y + p2 * v2.y) * inv;
        o[2] = (p0 * v0.z + p1 * v1.z + p2 * v2.z) * inv;
        o[3] = (p0 * v0.w + p1 * v1.w + p2 * v2.w) * inv;
    }
    {
        float4 k0 = rm[1], k1 = rc[1], k2 = rp[1];
        float s0 = 0.5f * dot4(qh1, k0), s1 = 0.5f * dot4(qh1, k1), s2 = 0.5f * dot4(qh1, k2);
        float mm = fmaxf(s0, fmaxf(s1, s2));
        float p0 = __expf(s0 - mm), p1 = __expf(s1 - mm), p2 = __expf(s2 - mm);
        float inv = 1.f / (p0 + p1 + p2);
        float4 v0 = rm[3], v1 = rc[3], v2 = rp[3];
        o[4] = (p0 * v0.x + p1 * v1.x + p2 * v2.x) * inv;
        o[5] = (p0 * v0.y + p1 * v1.y + p2 * v2.y) * inv;
        o[6] = (p0 * v0.z + p1 * v1.z + p2 * v2.z) * inv;
        o[7] = (p0 * v0.w + p1 * v1.w + p2 * v2.w) * inv;
    }

    // ---- out proj + residual + LN + safe + logit
    float4 o0 = make_float4(o[0], o[1], o[2], o[3]);
    float4 o1 = make_float4(o[4], o[5], o[6], o[7]);
    float x[8];
    float mu = 0.f;
    #pragma unroll
    for (int j = 0; j < 8; ++j) {
        const float4* wr = (const float4*)&sW[216 + 8 * j];
        float a = dot4(o0, wr[0]) + dot4(o1, wr[1]) + sW[280 + j];
        x[j] = safef(emb[j] + a);
        mu += x[j];
    }
    mu *= 0.125f;
    float var = 0.f;
    #pragma unroll
    for (int j = 0; j < 8; ++j) { float d = x[j] - mu; var += d * d; }
    var *= 0.125f;
    float rs = rsqrtf(var + 1e-5f);
    float e2[8];
    float lg = sW[344];
    #pragma unroll
    for (int j = 0; j < 8; ++j) {
        e2[j] = safef((x[j] - mu) * rs * sW[320 + j] + sW[328 + j]);
        lg += e2[j] * sW[336 + j];
    }
    lg = safef(lg);

    // ---- softmax over L=256 within block
    float mval = lg;
    #pragma unroll
    for (int off = 16; off; off >>= 1) mval = fmaxf(mval, __shfl_xor_sync(FULLMASK, mval, off));
    if (lane == 0) red[warp] = mval;
    __syncthreads();                                       // (5)
    float M = red[0];
    #pragma unroll
    for (int w = 1; w < 8; ++w) M = fmaxf(M, red[w]);
    float ev = __expf(lg - M);
    float sv = ev;
    #pragma unroll
    for (int off = 16; off; off >>= 1) sv += __shfl_xor_sync(FULLMASK, sv, off);
    if (lane == 0) red2[warp] = sv;
    __syncthreads();                                       // (6)
    float S = 0.f;
    #pragma unroll
    for (int w = 0; w < 8; ++w) S += red2[w];
    float wgt = ev / S;

    // ---- pooled = sum_i wgt_i * e2_i
    #pragma unroll
    for (int j = 0; j < 8; ++j) {
        float v = wgt * e2[j];
        #pragma unroll
        for (int off = 16; off; off >>= 1) v += __shfl_down_sync(FULLMASK, v, off);
        if (lane == 0) wred[warp * 8 + j] = v;
    }
    __syncthreads();                                       // (7)

    // ---- warp 0: pooled -> LN -> MLP -> cyc, then ia qkv
    if (tid < 32) {
        float p[8];
        #pragma unroll
        for (int j = 0; j < 8; ++j) {
            float a = 0.f;
            #pragma unroll
            for (int w = 0; w < 8; ++w) a += wred[w * 8 + j];
            p[j] = a;
        }
        float pm = 0.f;
        #pragma unroll
        for (int j = 0; j < 8; ++j) pm += p[j];
        pm *= 0.125f;
        float pv = 0.f;
        #pragma unroll
        for (int j = 0; j < 8; ++j) { float d = p[j] - pm; pv += d * d; }
        pv *= 0.125f;
        float prs = rsqrtf(pv + 1e-5f);
        float h[8];
        #pragma unroll
        for (int j = 0; j < 8; ++j)
            h[j] = (p[j] - pm) * prs * sW[352 + j] + sW[360 + j];
        float h1[8];
        #pragma unroll
        for (int j = 0; j < 8; ++j) {
            float s = sW[432 + j];
            #pragma unroll
            for (int k = 0; k < 8; ++k) s += h[k] * sW[368 + j * 8 + k];
            h1[j] = fmaxf(s, 0.f);
        }
        float cy[8];
        #pragma unroll
        for (int j = 0; j < 8; ++j) {
            float s = sW[504 + j];
            #pragma unroll
            for (int k = 0; k < 8; ++k) s += h1[k] * sW[440 + j * 8 + k];
            cy[j] = safef(s);
        }
        if (tid < 8) g_cyc[c * 8 + tid] = cy[tid];
        if (tid < 24) {
            float s = sW[704 + tid];
            #pragma unroll
            for (int k = 0; k < 8; ++k) s += cy[k] * sW[512 + tid * 8 + k];
            int j = tid & 7;
            if (tid < 8)       g_q[c * 8 + j] = s;
            else if (tid < 16) g_k[c * 8 + j] = s;
            else               g_v[c * 8 + j] = s;
        }
    }
}

// =====================================================================
// K2 (+ fused K3): dense attention over 1024 tokens, TWO-PASS softmax.
// 256 blocks x 4 warps, one query per warp, K/V read via LDG (L1-hot,
// no smem, no barriers in main body). Last block runs final pool+MLP.
// =====================================================================
__global__ void __launch_bounds__(128) coll_attn_kernel(
    const float* __restrict__ ia_out_w, const float* __restrict__ ia_out_b,
    const float* __restrict__ in_g, const float* __restrict__ in_b,
    const float* __restrict__ is_w, const float* __restrict__ is_b,
    const float* __restrict__ tp_ln_g, const float* __restrict__ tp_ln_b,
    const float* __restrict__ tp_w1, const float* __restrict__ tp_b1,
    const float* __restrict__ tp_w2, const float* __restrict__ tp_b2,
    float* __restrict__ out)
{
    __shared__ float fr1[4], fr2[4], fp[32];
    __shared__ int s_last;

    int tid = threadIdx.x, lane = tid & 31, warp = tid >> 5;
    int qi = blockIdx.x * 4 + warp;

    const float4* gq = (const float4*)g_q;
    const float4* gk = (const float4*)g_k;
    const float4* gv = (const float4*)g_v;
    float4 q0 = gq[qi * 2], q1 = gq[qi * 2 + 1];
    // fold the 1/sqrt(d)=0.5 scale into q
    q0.x *= 0.5f; q0.y *= 0.5f; q0.z *= 0.5f; q0.w *= 0.5f;
    q1.x *= 0.5f; q1.y *= 0.5f; q1.z *= 0.5f; q1.w *= 0.5f;

    // ---- pass 1: max of scores (no exp -> no dependency chain)
    float M0 = -3.402823466e38f, M1 = -3.402823466e38f;
    #pragma unroll 8
    for (int it = 0; it < 32; ++it) {
        int t = it * 32 + lane;
        float4 k0 = __ldg(gk + t * 2);
        float4 k1 = __ldg(gk + t * 2 + 1);
        M0 = fmaxf(M0, dot4(q0, k0));
        M1 = fmaxf(M1, dot4(q1, k1));
    }
    #pragma unroll
    for (int off = 16; off; off >>= 1) {
        M0 = fmaxf(M0, __shfl_xor_sync(FULLMASK, M0, off));
        M1 = fmaxf(M1, __shfl_xor_sync(FULLMASK, M1, off));
    }

    // ---- pass 2: independent exp + accumulate (fully pipelined)
    float l0 = 0.f, l1 = 0.f;
    float4 a0 = make_float4(0, 0, 0, 0), a1 = make_float4(0, 0, 0, 0);
    #pragma unroll 4
    for (int it = 0; it < 32; ++it) {
        int t = it * 32 + lane;
        float4 k0 = __ldg(gk + t * 2);
        float4 k1 = __ldg(gk + t * 2 + 1);
        float4 v0 = __ldg(gv + t * 2);
        float4 v1 = __ldg(gv + t * 2 + 1);
        float p0 = __expf(dot4(q0, k0) - M0);
        float p1 = __expf(dot4(q1, k1) - M1);
        l0 += p0; l1 += p1;
        a0.x += p0 * v0.x; a0.y += p0 * v0.y; a0.z += p0 * v0.z; a0.w += p0 * v0.w;
        a1.x += p1 * v1.x; a1.y += p1 * v1.y; a1.z += p1 * v1.z; a1.w += p1 * v1.w;
    }

    // ---- pure-sum warp reduction (10 floats, no exps)
    #pragma unroll
    for (int off = 16; off; off >>= 1) {
        l0   += __shfl_down_sync(FULLMASK, l0, off);
        l1   += __shfl_down_sync(FULLMASK, l1, off);
        a0.x += __shfl_down_sync(FULLMASK, a0.x, off);
        a0.y += __shfl_down_sync(FULLMASK, a0.y, off);
        a0.z += __shfl_down_sync(FULLMASK, a0.z, off);
        a0.w += __shfl_down_sync(FULLMASK, a0.w, off);
        a1.x += __shfl_down_sync(FULLMASK, a1.x, off);
        a1.y += __shfl_down_sync(FULLMASK, a1.y, off);
        a1.z += __shfl_down_sync(FULLMASK, a1.z, off);
        a1.w += __shfl_down_sync(FULLMASK, a1.w, off);
    }

    if (lane == 0) {
        float inv0 = 1.f / l0, inv1 = 1.f / l1;
        float o[8] = { a0.x * inv0, a0.y * inv0, a0.z * inv0, a0.w * inv0,
                       a1.x * inv1, a1.y * inv1, a1.z * inv1, a1.w * inv1 };
        float x[8];
        float mu = 0.f;
        #pragma unroll
        for (int j = 0; j < 8; ++j) {
            float s = __ldg(ia_out_b + j);
            #pragma unroll
            for (int k = 0; k < 8; ++k) s += o[k] * __ldg(ia_out_w + j * 8 + k);
            x[j] = safef(g_cyc[qi * 8 + j] + s);
            mu += x[j];
        }
        mu *= 0.125f;
        float var = 0.f;
        #pragma unroll
        for (int j = 0; j < 8; ++j) { float d = x[j] - mu; var += d * d; }
        var *= 0.125f;
        float rs = rsqrtf(var + 1e-5f);
        float lgv = __ldg(is_b);
        #pragma unroll
        for (int j = 0; j < 8; ++j) {
            float cj = safef((x[j] - mu) * rs * __ldg(in_g + j) + __ldg(in_b + j));
            g_coll[qi * 8 + j] = cj;
            lgv += cj * __ldg(is_w + j);
        }
        g_lg[qi] = safef(lgv);
    }

    // ---- last-block-done handoff -> fused K3
    __syncthreads();
    if (tid == 0) {
        __threadfence();
        int old = atomicAdd(&g_cnt, 1);
        s_last = (old == (int)gridDim.x - 1) ? 1 : 0;
    }
    __syncthreads();
    if (!s_last) return;

    if (tid == 0) g_cnt = 0;   // reset for next graph replay
    __threadfence();

    // ---- K3: global softmax pool over 1024 tokens + final LN + MLP
    float lgs[8];
    #pragma unroll
    for (int i = 0; i < 8; ++i) lgs[i] = g_lg[tid + i * 128];
    float mv = lgs[0];
    #pragma unroll
    for (int i = 1; i < 8; ++i) mv = fmaxf(mv, lgs[i]);
    #pragma unroll
    for (int off = 16; off; off >>= 1) mv = fmaxf(mv, __shfl_xor_sync(FULLMASK, mv, off));
    if (lane == 0) fr1[warp] = mv;
    __syncthreads();
    float M = fmaxf(fmaxf(fr1[0], fr1[1]), fmaxf(fr1[2], fr1[3]));
    float e[8];
    float ssum = 0.f;
    #pragma unroll
    for (int i = 0; i < 8; ++i) { e[i] = __expf(lgs[i] - M); ssum += e[i]; }
    float sv = ssum;
    #pragma unroll
    for (int off = 16; off; off >>= 1) sv += __shfl_xor_sync(FULLMASK, sv, off);
    if (lane == 0) fr2[warp] = sv;
    __syncthreads();
    float S = fr2[0] + fr2[1] + fr2[2] + fr2[3];

    const float4* gc = (const float4*)g_coll;
    float acc[8] = {0, 0, 0, 0, 0, 0, 0, 0};
    #pragma unroll
    for (int i = 0; i < 8; ++i) {
        int tok = tid + i * 128;
        float4 c0 = gc[tok * 2], c1 = gc[tok * 2 + 1];
        acc[0] += e[i] * c0.x; acc[1] += e[i] * c0.y;
        acc[2] += e[i] * c0.z; acc[3] += e[i] * c0.w;
        acc[4] += e[i] * c1.x; acc[5] += e[i] * c1.y;
        acc[6] += e[i] * c1.z; acc[7] += e[i] * c1.w;
    }
    #pragma unroll
    for (int j = 0; j < 8; ++j) {
        float v = acc[j];
        #pragma unroll
        for (int off = 16; off; off >>= 1) v += __shfl_down_sync(FULLMASK, v, off);
        if (lane == 0) fp[warp * 8 + j] = v;
    }
    __syncthreads();
    if (tid == 0) {
        float invS = 1.f / S;
        float p[8];
        #pragma unroll
        for (int j = 0; j < 8; ++j)
            p[j] = (fp[j] + fp[8 + j] + fp[16 + j] + fp[24 + j]) * invS;
        float mu = 0.f;
        #pragma unroll
        for (int j = 0; j < 8; ++j) mu += p[j];
        mu *= 0.125f;
        float var = 0.f;
        #pragma unroll
        for (int j = 0; j < 8; ++j) { float d = p[j] - mu; var += d * d; }
        var *= 0.125f;
        float rs = rsqrtf(var + 1e-5f);
        float h[8];
        #pragma unroll
        for (int j = 0; j < 8; ++j)
            h[j] = (p[j] - mu) * rs * __ldg(tp_ln_g + j) + __ldg(tp_ln_b + j);
        float h1[8];
        #pragma unroll
        for (int j = 0; j < 8; ++j) {
            float a = __ldg(tp_b1 + j);
            #pragma unroll
            for (int k = 0; k < 8; ++k) a += h[k] * __ldg(tp_w1 + j * 8 + k);
            h1[j] = fmaxf(a, 0.f);
        }
        #pragma unroll
        for (int j = 0; j < 8; ++j) {
            float a = __ldg(tp_b2 + j);
            #pragma unroll
            for (int k = 0; k < 8; ++k) a += h1[k] * __ldg(tp_w2 + j * 8 + k);
            out[j] = safef(a);
        }
    }
}

// =====================================================================
extern "C" void kernel_launch(void* const* d_in, const int* in_sizes, int n_in,
                              void* d_out, int out_size) {
    const float* df      = (const float*)d_in[0];
    const float* de_w    = (const float*)d_in[1];
    const float* de_b    = (const float*)d_in[2];
    const float* ca_in_w = (const float*)d_in[3];
    const float* ca_in_b = (const float*)d_in[4];
    const float* ca_out_w= (const float*)d_in[5];
    const float* ca_out_b= (const float*)d_in[6];
    const float* cn_g    = (const float*)d_in[7];
    const float* cn_b    = (const float*)d_in[8];
    const float* cs_w    = (const float*)d_in[9];
    const float* cs_b    = (const float*)d_in[10];
    const float* cp_ln_g = (const float*)d_in[11];
    const float* cp_ln_b = (const float*)d_in[12];
    const float* cp_w1   = (const float*)d_in[13];
    const float* cp_b1   = (const float*)d_in[14];
    const float* cp_w2   = (const float*)d_in[15];
    const float* cp_b2   = (const float*)d_in[16];
    const float* ia_in_w = (const float*)d_in[17];
    const float* ia_in_b = (const float*)d_in[18];
    const float* ia_out_w= (const float*)d_in[19];
    const float* ia_out_b= (const float*)d_in[20];
    const float* in_g    = (const float*)d_in[21];
    const float* in_b    = (const float*)d_in[22];
    const float* is_w    = (const float*)d_in[23];
    const float* is_b    = (const float*)d_in[24];
    const float* tp_ln_g = (const float*)d_in[25];
    const float* tp_ln_b = (const float*)d_in[26];
    const float* tp_w1   = (const float*)d_in[27];
    const float* tp_b1   = (const float*)d_in[28];
    const float* tp_w2   = (const float*)d_in[29];
    const float* tp_b2   = (const float*)d_in[30];

    cycle_kernel<<<1024, 256>>>(df, de_w, de_b, ca_in_w, ca_in_b, ca_out_w, ca_out_b,
                                cn_g, cn_b, cs_w, cs_b, cp_ln_g, cp_ln_b,
                                cp_w1, cp_b1, cp_w2, cp_b2, ia_in_w, ia_in_b);
    coll_attn_kernel<<<256, 128>>>(ia_out_w, ia_out_b, in_g, in_b, is_w, is_b,
                                   tp_ln_g, tp_ln_b, tp_w1, tp_b1, tp_w2, tp_b2,
                                   (float*)d_out);
}

// round 4
// speedup vs baseline: 1.2904x; 1.2904x over previous
#include <cuda_runtime.h>

#define FULLMASK 0xffffffffu

// ---------------- scratch (device globals; no allocations allowed) ----------
__device__ float g_cyc[1024 * 8];
__device__ float g_q[1024 * 8];
__device__ float g_k[1024 * 8];
__device__ float g_v[1024 * 8];
__device__ float g_coll[1024 * 8];
__device__ float g_lg[1024];
__device__ int   g_cnt = 0;

__device__ __forceinline__ float safef(float x) {
    x = (x != x) ? 0.f : x;                    // nan -> 0
    return fminf(fmaxf(x, -10000.f), 10000.f); // +-inf -> clamp
}
__device__ __forceinline__ float dot4(float4 a, float4 b) {
    return a.x * b.x + a.y * b.y + a.z * b.z + a.w * b.w;
}

// =====================================================================
// K1: per-cycle pipeline. 1 block = 1 cycle, 256 threads = 256 darts.
// =====================================================================
__global__ void __launch_bounds__(256) cycle_kernel(
    const float* __restrict__ df,
    const float* __restrict__ de_w, const float* __restrict__ de_b,
    const float* __restrict__ ca_in_w, const float* __restrict__ ca_in_b,
    const float* __restrict__ ca_out_w, const float* __restrict__ ca_out_b,
    const float* __restrict__ cn_g, const float* __restrict__ cn_b,
    const float* __restrict__ cs_w, const float* __restrict__ cs_b,
    const float* __restrict__ cp_ln_g, const float* __restrict__ cp_ln_b,
    const float* __restrict__ cp_w1, const float* __restrict__ cp_b1,
    const float* __restrict__ cp_w2, const float* __restrict__ cp_b2,
    const float* __restrict__ ia_in_w, const float* __restrict__ ia_in_b)
{
    __shared__ float sdx[256], sdy[256];
    __shared__ __align__(16) float skv[256 * 20];   // per dart: k[0..7], v[8..15], pad4
    __shared__ __align__(16) float sW[736];
    __shared__ float red[8], red2[8], wred[64];

    int tid = threadIdx.x;
    int lane = tid & 31, warp = tid >> 5;
    int c = blockIdx.x;

    // ---- stage ALL per-block weights into shared
    if (tid < 192) { sW[tid] = ca_in_w[tid]; sW[512 + tid] = ia_in_w[tid]; }
    if (tid < 64)  { sW[216 + tid] = ca_out_w[tid]; sW[368 + tid] = cp_w1[tid]; sW[440 + tid] = cp_w2[tid]; }
    if (tid < 24)  { sW[192 + tid] = ca_in_b[tid]; sW[288 + tid] = de_w[tid]; sW[704 + tid] = ia_in_b[tid]; }
    if (tid < 8) {
        sW[280 + tid] = ca_out_b[tid];
        sW[312 + tid] = de_b[tid];
        sW[320 + tid] = cn_g[tid];
        sW[328 + tid] = cn_b[tid];
        sW[336 + tid] = cs_w[tid];
        sW[352 + tid] = cp_ln_g[tid];
        sW[360 + tid] = cp_ln_b[tid];
        sW[432 + tid] = cp_b1[tid];
        sW[504 + tid] = cp_b2[tid];
    }
    if (tid == 0) sW[344] = cs_b[0];

    // ---- coalesced load of this cycle's darts (skv as staging)
    const float* base = df + (size_t)c * 768;
    skv[tid]       = base[tid];
    skv[tid + 256] = base[tid + 256];
    skv[tid + 512] = base[tid + 512];
    __syncthreads();                                       // (1)

    float dx = skv[3 * tid];
    float dy = skv[3 * tid + 1];
    sdx[tid] = dx; sdy[tid] = dy;

    // ---- warp-shuffle inclusive scan for prefix sums (vertices)
    float sx = dx, sy = dy;
    #pragma unroll
    for (int off = 1; off < 32; off <<= 1) {
        float tx = __shfl_up_sync(FULLMASK, sx, off);
        float ty = __shfl_up_sync(FULLMASK, sy, off);
        if (lane >= off) { sx += tx; sy += ty; }
    }
    if (lane == 31) { red[warp] = sx; red2[warp] = sy; }
    __syncthreads();                                       // (2)
    float bx = 0.f, by = 0.f;
    #pragma unroll
    for (int w = 0; w < 8; ++w) {
        if (w < warp) { bx += red[w]; by += red2[w]; }
    }
    float Vx = bx + sx - dx, Vy = by + sy - dy;            // exclusive prefix
    float cr = (tid < 255) ? (Vx * dy - Vy * dx) : 0.f;
    #pragma unroll
    for (int off = 16; off; off >>= 1) cr += __shfl_xor_sync(FULLMASK, cr, off);
    if (lane == 0) wred[warp] = cr;
    __syncthreads();                                       // (3)
    float area = 0.f;
    #pragma unroll
    for (int w = 0; w < 8; ++w) area += wred[w];
    bool flip = area < 0.f;

    float ex = flip ? -sdx[255 - tid] : dx;
    float ey = flip ? -sdy[255 - tid] : dy;
    float fn = safef(sqrtf(ex * ex + ey * ey));
    float fx = safef(ex), fy = safef(ey);

    // ---- dart embed: relu(feats @ de_w.T + de_b), safe
    float emb[8];
    #pragma unroll
    for (int j = 0; j < 8; ++j) {
        float e = fx * sW[288 + 3 * j] + fy * sW[288 + 3 * j + 1] + fn * sW[288 + 3 * j + 2] + sW[312 + j];
        emb[j] = safef(fmaxf(e, 0.f));
    }

    // ---- qkv (24x8). q in regs; k,v into skv row.
    const float4* w4 = (const float4*)sW;
    float4 e0 = make_float4(emb[0], emb[1], emb[2], emb[3]);
    float4 e1 = make_float4(emb[4], emb[5], emb[6], emb[7]);
    float qv[8];
    #pragma unroll
    for (int j = 0; j < 8; ++j)
        qv[j] = dot4(e0, w4[2 * j]) + dot4(e1, w4[2 * j + 1]) + sW[192 + j];
    float* myrow = &skv[tid * 20];
    #pragma unroll
    for (int j = 8; j < 24; ++j)
        myrow[j - 8] = dot4(e0, w4[2 * j]) + dot4(e1, w4[2 * j + 1]) + sW[192 + j];
    __syncthreads();                                       // (4)

    // ---- 3-neighbor attention
    int im = (tid + 255) & 255, ip = (tid + 1) & 255;
    const float4* rm = (const float4*)&skv[im * 20];
    const float4* rc = (const float4*)&skv[tid * 20];
    const float4* rp = (const float4*)&skv[ip * 20];
    float4 qh0 = make_float4(qv[0], qv[1], qv[2], qv[3]);
    float4 qh1 = make_float4(qv[4], qv[5], qv[6], qv[7]);
    float o[8];
    {
        float4 k0 = rm[0], k1 = rc[0], k2 = rp[0];
        float s0 = 0.5f * dot4(qh0, k0), s1 = 0.5f * dot4(qh0, k1), s2 = 0.5f * dot4(qh0, k2);
        float mm = fmaxf(s0, fmaxf(s1, s2));
        float p0 = __expf(s0 - mm), p1 = __expf(s1 - mm), p2 = __expf(s2 - mm);
        float inv = 1.f / (p0 + p1 + p2);
        float4 v0 = rm[2], v1 = rc[2], v2 = rp[2];
        o[0] = (p0 * v0.x + p1 * v1.x + p2 * v2.x) * inv;
        o[1] = (p0 * v0.y + p1 * v1.y + p2 * v2.y) * inv;
        o[2] = (p0 * v0.z + p1 * v1.z + p2 * v2.z) * inv;
        o[3] = (p0 * v0.w + p1 * v1.w + p2 * v2.w) * inv;
    }
    {
        float4 k0 = rm[1], k1 = rc[1], k2 = rp[1];
        float s0 = 0.5f * dot4(qh1, k0), s1 = 0.5f * dot4(qh1, k1), s2 = 0.5f * dot4(qh1, k2);
        float mm = fmaxf(s0, fmaxf(s1, s2));
        float p0 = __expf(s0 - mm), p1 = __expf(s1 - mm), p2 = __expf(s2 - mm);
        float inv = 1.f / (p0 + p1 + p2);
        float4 v0 = rm[3], v1 = rc[3], v2 = rp[3];
        o[4] = (p0 * v0.x + p1 * v1.x + p2 * v2.x) * inv;
        o[5] = (p0 * v0.y + p1 * v1.y + p2 * v2.y) * inv;
        o[6] = (p0 * v0.z + p1 * v1.z + p2 * v2.z) * inv;
        o[7] = (p0 * v0.w + p1 * v1.w + p2 * v2.w) * inv;
    }

    // ---- out proj + residual + LN + safe + logit
    float4 o0 = make_float4(o[0], o[1], o[2], o[3]);
    float4 o1 = make_float4(o[4], o[5], o[6], o[7]);
    float x[8];
    float mu = 0.f;
    #pragma unroll
    for (int j = 0; j < 8; ++j) {
        const float4* wr = (const float4*)&sW[216 + 8 * j];
        float a = dot4(o0, wr[0]) + dot4(o1, wr[1]) + sW[280 + j];
        x[j] = safef(emb[j] + a);
        mu += x[j];
    }
    mu *= 0.125f;
    float var = 0.f;
    #pragma unroll
    for (int j = 0; j < 8; ++j) { float d = x[j] - mu; var += d * d; }
    var *= 0.125f;
    float rs = rsqrtf(var + 1e-5f);
    float e2[8];
    float lg = sW[344];
    #pragma unroll
    for (int j = 0; j < 8; ++j) {
        e2[j] = safef((x[j] - mu) * rs * sW[320 + j] + sW[328 + j]);
        lg += e2[j] * sW[336 + j];
    }
    lg = safef(lg);

    // ---- softmax over L=256 within block
    float mval = lg;
    #pragma unroll
    for (int off = 16; off; off >>= 1) mval = fmaxf(mval, __shfl_xor_sync(FULLMASK, mval, off));
    if (lane == 0) red[warp] = mval;
    __syncthreads();                                       // (5)
    float M = red[0];
    #pragma unroll
    for (int w = 1; w < 8; ++w) M = fmaxf(M, red[w]);
    float ev = __expf(lg - M);
    float sv = ev;
    #pragma unroll
    for (int off = 16; off; off >>= 1) sv += __shfl_xor_sync(FULLMASK, sv, off);
    if (lane == 0) red2[warp] = sv;
    __syncthreads();                                       // (6)
    float S = 0.f;
    #pragma unroll
    for (int w = 0; w < 8; ++w) S += red2[w];
    float wgt = ev / S;

    // ---- pooled = sum_i wgt_i * e2_i
    #pragma unroll
    for (int j = 0; j < 8; ++j) {
        float v = wgt * e2[j];
        #pragma unroll
        for (int off = 16; off; off >>= 1) v += __shfl_down_sync(FULLMASK, v, off);
        if (lane == 0) wred[warp * 8 + j] = v;
    }
    __syncthreads();                                       // (7)

    // ---- warp 0: pooled -> LN -> MLP -> cyc, then ia qkv
    if (tid < 32) {
        float p[8];
        #pragma unroll
        for (int j = 0; j < 8; ++j) {
            float a = 0.f;
            #pragma unroll
            for (int w = 0; w < 8; ++w) a += wred[w * 8 + j];
            p[j] = a;
        }
        float pm = 0.f;
        #pragma unroll
        for (int j = 0; j < 8; ++j) pm += p[j];
        pm *= 0.125f;
        float pv = 0.f;
        #pragma unroll
        for (int j = 0; j < 8; ++j) { float d = p[j] - pm; pv += d * d; }
        pv *= 0.125f;
        float prs = rsqrtf(pv + 1e-5f);
        float h[8];
        #pragma unroll
        for (int j = 0; j < 8; ++j)
            h[j] = (p[j] - pm) * prs * sW[352 + j] + sW[360 + j];
        float h1[8];
        #pragma unroll
        for (int j = 0; j < 8; ++j) {
            float s = sW[432 + j];
            #pragma unroll
            for (int k = 0; k < 8; ++k) s += h[k] * sW[368 + j * 8 + k];
            h1[j] = fmaxf(s, 0.f);
        }
        float cy[8];
        #pragma unroll
        for (int j = 0; j < 8; ++j) {
            float s = sW[504 + j];
            #pragma unroll
            for (int k = 0; k < 8; ++k) s += h1[k] * sW[440 + j * 8 + k];
            cy[j] = safef(s);
        }
        if (tid < 8) g_cyc[c * 8 + tid] = cy[tid];
        if (tid < 24) {
            float s = sW[704 + tid];
            #pragma unroll
            for (int k = 0; k < 8; ++k) s += cy[k] * sW[512 + tid * 8 + k];
            int j = tid & 7;
            if (tid < 8)       g_q[c * 8 + j] = s;
            else if (tid < 16) g_k[c * 8 + j] = s;
            else               g_v[c * 8 + j] = s;
        }
    }
}

// =====================================================================
// K2 (+ fused K3): dense attention over 1024 tokens.
// 128 blocks x 8 warps; one query/warp; K/V staged in 32KB smem chunks
// (shared by all warps); TWO-PASS softmax per chunk (max pass with no
// exp chain, then pipelined exp+acc), one rescale merge between chunks.
// Last-finished block runs the global pool + final MLP.
// =====================================================================
__global__ void __launch_bounds__(256) coll_attn_kernel(
    const float* __restrict__ ia_out_w, const float* __restrict__ ia_out_b,
    const float* __restrict__ in_g, const float* __restrict__ in_b,
    const float* __restrict__ is_w, const float* __restrict__ is_b,
    const float* __restrict__ tp_ln_g, const float* __restrict__ tp_ln_b,
    const float* __restrict__ tp_w1, const float* __restrict__ tp_b1,
    const float* __restrict__ tp_w2, const float* __restrict__ tp_b2,
    float* __restrict__ out)
{
    __shared__ float4 skh0[512], skh1[512], svh0[512], svh1[512]; // 32KB
    __shared__ float fr1[8], fr2[8], fp[64];
    __shared__ int s_last;

    int tid = threadIdx.x, lane = tid & 31, warp = tid >> 5;
    int qi = blockIdx.x * 8 + warp;

    const float4* gq = (const float4*)g_q;
    const float4* gk = (const float4*)g_k;
    const float4* gv = (const float4*)g_v;
    float4 q0 = gq[qi * 2], q1 = gq[qi * 2 + 1];
    // fold the 1/sqrt(d)=0.5 scale into q
    q0.x *= 0.5f; q0.y *= 0.5f; q0.z *= 0.5f; q0.w *= 0.5f;
    q1.x *= 0.5f; q1.y *= 0.5f; q1.z *= 0.5f; q1.w *= 0.5f;

    float m0 = -3.402823466e38f, m1 = -3.402823466e38f;
    float l0 = 0.f, l1 = 0.f;
    float4 a0 = make_float4(0, 0, 0, 0), a1 = make_float4(0, 0, 0, 0);

    for (int ch = 0; ch < 2; ++ch) {
        int base = ch * 512;
        for (int t = tid; t < 512; t += 256) {
            skh0[t] = gk[(base + t) * 2];
            skh1[t] = gk[(base + t) * 2 + 1];
            svh0[t] = gv[(base + t) * 2];
            svh1[t] = gv[(base + t) * 2 + 1];
        }
        __syncthreads();

        // ---- pass 1: chunk max (no exp -> short fmax chain, 2-head ILP)
        float cA0 = -3.402823466e38f, cB0 = -3.402823466e38f;
        float cA1 = -3.402823466e38f, cB1 = -3.402823466e38f;
        #pragma unroll
        for (int it = 0; it < 16; it += 2) {
            int t0 = it * 32 + lane, t1 = t0 + 32;
            cA0 = fmaxf(cA0, dot4(q0, skh0[t0]));
            cB0 = fmaxf(cB0, dot4(q0, skh0[t1]));
            cA1 = fmaxf(cA1, dot4(q1, skh1[t0]));
            cB1 = fmaxf(cB1, dot4(q1, skh1[t1]));
        }
        float cm0 = fmaxf(cA0, cB0), cm1 = fmaxf(cA1, cB1);
        #pragma unroll
        for (int off = 16; off; off >>= 1) {
            cm0 = fmaxf(cm0, __shfl_xor_sync(FULLMASK, cm0, off));
            cm1 = fmaxf(cm1, __shfl_xor_sync(FULLMASK, cm1, off));
        }

        // ---- merge chunk max into running stats (one rescale)
        float nm0 = fmaxf(m0, cm0), nm1 = fmaxf(m1, cm1);
        float sc0 = __expf(m0 - nm0), sc1 = __expf(m1 - nm1);
        l0 *= sc0; a0.x *= sc0; a0.y *= sc0; a0.z *= sc0; a0.w *= sc0;
        l1 *= sc1; a1.x *= sc1; a1.y *= sc1; a1.z *= sc1; a1.w *= sc1;
        m0 = nm0; m1 = nm1;

        // ---- pass 2: independent exp + accumulate (pipelined)
        #pragma unroll
        for (int it = 0; it < 16; ++it) {
            int t = it * 32 + lane;
            float4 k0 = skh0[t], k1 = skh1[t];
            float4 v0 = svh0[t], v1 = svh1[t];
            float p0 = __expf(dot4(q0, k0) - m0);
            float p1 = __expf(dot4(q1, k1) - m1);
            l0 += p0; l1 += p1;
            a0.x += p0 * v0.x; a0.y += p0 * v0.y; a0.z += p0 * v0.z; a0.w += p0 * v0.w;
            a1.x += p1 * v1.x; a1.y += p1 * v1.y; a1.z += p1 * v1.z; a1.w += p1 * v1.w;
        }
        __syncthreads();
    }

    // ---- pure-sum warp reduction (10 floats, same m on all lanes)
    #pragma unroll
    for (int off = 16; off; off >>= 1) {
        l0   += __shfl_down_sync(FULLMASK, l0, off);
        l1   += __shfl_down_sync(FULLMASK, l1, off);
        a0.x += __shfl_down_sync(FULLMASK, a0.x, off);
        a0.y += __shfl_down_sync(FULLMASK, a0.y, off);
        a0.z += __shfl_down_sync(FULLMASK, a0.z, off);
        a0.w += __shfl_down_sync(FULLMASK, a0.w, off);
        a1.x += __shfl_down_sync(FULLMASK, a1.x, off);
        a1.y += __shfl_down_sync(FULLMASK, a1.y, off);
        a1.z += __shfl_down_sync(FULLMASK, a1.z, off);
        a1.w += __shfl_down_sync(FULLMASK, a1.w, off);
    }

    if (lane == 0) {
        float inv0 = 1.f / l0, inv1 = 1.f / l1;
        float o[8] = { a0.x * inv0, a0.y * inv0, a0.z * inv0, a0.w * inv0,
                       a1.x * inv1, a1.y * inv1, a1.z * inv1, a1.w * inv1 };
        float x[8];
        float mu = 0.f;
        #pragma unroll
        for (int j = 0; j < 8; ++j) {
            float s = __ldg(ia_out_b + j);
            #pragma unroll
            for (int k = 0; k < 8; ++k) s += o[k] * __ldg(ia_out_w + j * 8 + k);
            x[j] = safef(g_cyc[qi * 8 + j] + s);
            mu += x[j];
        }
        mu *= 0.125f;
        float var = 0.f;
        #pragma unroll
        for (int j = 0; j < 8; ++j) { float d = x[j] - mu; var += d * d; }
        var *= 0.125f;
        float rs = rsqrtf(var + 1e-5f);
        float lgv = __ldg(is_b);
        #pragma unroll
        for (int j = 0; j < 8; ++j) {
            float cj = safef((x[j] - mu) * rs * __ldg(in_g + j) + __ldg(in_b + j));
            g_coll[qi * 8 + j] = cj;
            lgv += cj * __ldg(is_w + j);
        }
        g_lg[qi] = safef(lgv);
    }

    // ---- last-block-done handoff -> fused K3
    __syncthreads();
    if (tid == 0) {
        __threadfence();
        int old = atomicAdd(&g_cnt, 1);
        s_last = (old == (int)gridDim.x - 1) ? 1 : 0;
    }
    __syncthreads();
    if (!s_last) return;

    if (tid == 0) g_cnt = 0;   // reset for next graph replay
    __threadfence();

    // ---- K3: global softmax pool over 1024 tokens + final LN + MLP
    float lgs[4];
    #pragma unroll
    for (int i = 0; i < 4; ++i) lgs[i] = g_lg[tid + i * 256];
    float mv = fmaxf(fmaxf(lgs[0], lgs[1]), fmaxf(lgs[2], lgs[3]));
    #pragma unroll
    for (int off = 16; off; off >>= 1) mv = fmaxf(mv, __shfl_xor_sync(FULLMASK, mv, off));
    if (lane == 0) fr1[warp] = mv;
    __syncthreads();
    float M = fr1[0];
    #pragma unroll
    for (int w = 1; w < 8; ++w) M = fmaxf(M, fr1[w]);
    float e[4];
    float ssum = 0.f;
    #pragma unroll
    for (int i = 0; i < 4; ++i) { e[i] = __expf(lgs[i] - M); ssum += e[i]; }
    float sv = ssum;
    #pragma unroll
    for (int off = 16; off; off >>= 1) sv += __shfl_xor_sync(FULLMASK, sv, off);
    if (lane == 0) fr2[warp] = sv;
    __syncthreads();
    float S = 0.f;
    #pragma unroll
    for (int w = 0; w < 8; ++w) S += fr2[w];

    const float4* gc = (const float4*)g_coll;
    float acc[8] = {0, 0, 0, 0, 0, 0, 0, 0};
    #pragma unroll
    for (int i = 0; i < 4; ++i) {
        int tok = tid + i * 256;
        float4 c0 = gc[tok * 2], c1 = gc[tok * 2 + 1];
        acc[0] += e[i] * c0.x; acc[1] += e[i] * c0.y;
        acc[2] += e[i] * c0.z; acc[3] += e[i] * c0.w;
        acc[4] += e[i] * c1.x; acc[5] += e[i] * c1.y;
        acc[6] += e[i] * c1.z; acc[7] += e[i] * c1.w;
    }
    #pragma unroll
    for (int j = 0; j < 8; ++j) {
        float v = acc[j];
        #pragma unroll
        for (int off = 16; off; off >>= 1) v += __shfl_down_sync(FULLMASK, v, off);
        if (lane == 0) fp[warp * 8 + j] = v;
    }
    __syncthreads();
    if (tid == 0) {
        float invS = 1.f / S;
        float p[8];
        #pragma unroll
        for (int j = 0; j < 8; ++j) {
            float a = 0.f;
            #pragma unroll
            for (int w = 0; w < 8; ++w) a += fp[w * 8 + j];
            p[j] = a * invS;
        }
        float mu = 0.f;
        #pragma unroll
        for (int j = 0; j < 8; ++j) mu += p[j];
        mu *= 0.125f;
        float var = 0.f;
        #pragma unroll
        for (int j = 0; j < 8; ++j) { float d = p[j] - mu; var += d * d; }
        var *= 0.125f;
        float rs = rsqrtf(var + 1e-5f);
        float h[8];
        #pragma unroll
        for (int j = 0; j < 8; ++j)
            h[j] = (p[j] - mu) * rs * __ldg(tp_ln_g + j) + __ldg(tp_ln_b + j);
        float h1[8];
        #pragma unroll
        for (int j = 0; j < 8; ++j) {
            float a = __ldg(tp_b1 + j);
            #pragma unroll
            for (int k = 0; k < 8; ++k) a += h[k] * __ldg(tp_w1 + j * 8 + k);
            h1[j] = fmaxf(a, 0.f);
        }
        #pragma unroll
        for (int j = 0; j < 8; ++j) {
            float a = __ldg(tp_b2 + j);
            #pragma unroll
            for (int k = 0; k < 8; ++k) a += h1[k] * __ldg(tp_w2 + j * 8 + k);
            out[j] = safef(a);
        }
    }
}

// =====================================================================
extern "C" void kernel_launch(void* const* d_in, const int* in_sizes, int n_in,
                              void* d_out, int out_size) {
    const float* df      = (const float*)d_in[0];
    const float* de_w    = (const float*)d_in[1];
    const float* de_b    = (const float*)d_in[2];
    const float* ca_in_w = (const float*)d_in[3];
    const float* ca_in_b = (const float*)d_in[4];
    const float* ca_out_w= (const float*)d_in[5];
    const float* ca_out_b= (const float*)d_in[6];
    const float* cn_g    = (const float*)d_in[7];
    const float* cn_b    = (const float*)d_in[8];
    const float* cs_w    = (const float*)d_in[9];
    const float* cs_b    = (const float*)d_in[10];
    const float* cp_ln_g = (const float*)d_in[11];
    const float* cp_ln_b = (const float*)d_in[12];
    const float* cp_w1   = (const float*)d_in[13];
    const float* cp_b1   = (const float*)d_in[14];
    const float* cp_w2   = (const float*)d_in[15];
    const float* cp_b2   = (const float*)d_in[16];
    const float* ia_in_w = (const float*)d_in[17];
    const float* ia_in_b = (const float*)d_in[18];
    const float* ia_out_w= (const float*)d_in[19];
    const float* ia_out_b= (const float*)d_in[20];
    const float* in_g    = (const float*)d_in[21];
    const float* in_b    = (const float*)d_in[22];
    const float* is_w    = (const float*)d_in[23];
    const float* is_b    = (const float*)d_in[24];
    const float* tp_ln_g = (const float*)d_in[25];
    const float* tp_ln_b = (const float*)d_in[26];
    const float* tp_w1   = (const float*)d_in[27];
    const float* tp_b1   = (const float*)d_in[28];
    const float* tp_w2   = (const float*)d_in[29];
    const float* tp_b2   = (const float*)d_in[30];

    cycle_kernel<<<1024, 256>>>(df, de_w, de_b, ca_in_w, ca_in_b, ca_out_w, ca_out_b,
                                cn_g, cn_b, cs_w, cs_b, cp_ln_g, cp_ln_b,
                                cp_w1, cp_b1, cp_w2, cp_b2, ia_in_w, ia_in_b);
    coll_attn_kernel<<<128, 256>>>(ia_out_w, ia_out_b, in_g, in_b, is_w, is_b,
                                   tp_ln_g, tp_ln_b, tp_w1, tp_b1, tp_w2, tp_b2,
                                   (float*)d_out);
}